// round 8
// baseline (speedup 1.0000x reference)
#include <cuda_runtime.h>
#include <cuda_bf16.h>
#include <cstdint>
#include <stdint.h>
#include <math.h>

#define NN    8192
#define IN_F  512
#define HF    256
#define NEDGE 65536

// ---------------- scratch (device globals; no allocation allowed) ----------------
__device__ float g_Z [NN * HF];
__device__ float g_H1[NN * HF];
__device__ float g_H [NN * HF];   // h  (GCN on adj)
__device__ float g_Hb[NN * HF];   // h_ (GCN on sim graph)
__device__ float g_P [NN * 2 * HF];
__device__ float g_deg[NN];
__device__ float g_s2 [NN];
__device__ float g_w2v[IN_F];
__device__ float g_totA[HF];
__device__ float g_totB[HF];
__device__ float g_S16[HF];
__device__ int   g_hub[16];
__device__ int   g_hubflag[NN];
__device__ float g_acc;

// ---------------- small helpers ----------------
__device__ __forceinline__ unsigned sptr(const void* p) {
    return (unsigned)__cvta_generic_to_shared(p);
}
__device__ __forceinline__ void ldsm_x4(unsigned r[4], unsigned addr) {
    asm volatile("ldmatrix.sync.aligned.m8n8.x4.shared.b16 {%0,%1,%2,%3}, [%4];"
        : "=r"(r[0]), "=r"(r[1]), "=r"(r[2]), "=r"(r[3]) : "r"(addr));
}
__device__ __forceinline__ void ldsm_x4_t(unsigned r[4], unsigned addr) {
    asm volatile("ldmatrix.sync.aligned.m8n8.x4.trans.shared.b16 {%0,%1,%2,%3}, [%4];"
        : "=r"(r[0]), "=r"(r[1]), "=r"(r[2]), "=r"(r[3]) : "r"(addr));
}
__device__ __forceinline__ void mma16816(float c[4], const unsigned a[4], const unsigned b[2]) {
    asm volatile("mma.sync.aligned.m16n8k16.row.col.f32.bf16.bf16.f32 "
        "{%0,%1,%2,%3}, {%4,%5,%6,%7}, {%8,%9}, {%0,%1,%2,%3};"
        : "+f"(c[0]), "+f"(c[1]), "+f"(c[2]), "+f"(c[3])
        : "r"(a[0]), "r"(a[1]), "r"(a[2]), "r"(a[3]), "r"(b[0]), "r"(b[1]));
}

// ---------------- init ----------------
__global__ void init_kernel(float* deg, float* totA, float* totB, float* acc) {
    int i = blockIdx.x * blockDim.x + threadIdx.x;
    if (i < NN) deg[i] = 1.0f;           // +I contribution to column sums
    if (i < HF) { totA[i] = 0.f; totB[i] = 0.f; }
    if (i == 0) acc[0] = 0.f;
}

// deg[c] = 1 + sum_r adj[r][c]  (column sums of adj+I)
__global__ void deg_kernel(const float* __restrict__ adj, float* __restrict__ deg) {
    int c = blockIdx.x * 256 + threadIdx.x;
    size_t r0 = (size_t)blockIdx.y * 512;
    float s = 0.f;
    for (int r = 0; r < 512; r++) s += adj[(r0 + r) * NN + c];
    atomicAdd(&deg[c], s);
}

// ---------------- split-bf16 tensor-core GEMM, 128x128x32 CTA tile ----------------
// C = A@B in "effective fp32": Ahi*Bhi + Ahi*Blo + Alo*Bhi  (fp32 accum)
// MODE 0: C = A@B
// MODE 1: C = elu((A@B + Zadd)/deg[row])      [ (adj+I)Z normalized ]
template <int MODE>
__global__ void __launch_bounds__(256)
mma_gemm(const float* __restrict__ A, const float* __restrict__ B,
         float* __restrict__ C, int M, int N, int K,
         const float* __restrict__ Zadd, const float* __restrict__ deg)
{
    __shared__ __align__(16) __nv_bfloat16 Ah[128 * 32], Al[128 * 32];
    __shared__ __align__(16) __nv_bfloat16 Bh[32 * 128], Bl[32 * 128];

    const int tid  = threadIdx.x;
    const int lane = tid & 31;
    const int w    = tid >> 5;
    const int wm   = w & 1;        // 2 warps along M (64 rows each)
    const int wn   = w >> 1;       // 4 warps along N (32 cols each)
    const int row0 = blockIdx.y * 128;
    const int col0 = blockIdx.x * 128;

    float acc[4][4][4];
#pragma unroll
    for (int mt = 0; mt < 4; mt++)
#pragma unroll
        for (int nt = 0; nt < 4; nt++)
#pragma unroll
            for (int q = 0; q < 4; q++) acc[mt][nt][q] = 0.f;

    float4 pa[4], pb[4];
    const int nk = K >> 5;

    // prefetch tile 0
#pragma unroll
    for (int i = 0; i < 4; i++) {
        int v = tid + i * 256;
        int r = v >> 3, kq = (v & 7) << 2;
        pa[i] = *reinterpret_cast<const float4*>(A + (size_t)(row0 + r) * K + kq);
        int kr = v >> 5, nq = (v & 31) << 2;
        pb[i] = *reinterpret_cast<const float4*>(B + (size_t)kr * N + col0 + nq);
    }

    for (int kt = 0; kt < nk; kt++) {
        // store prefetched tile to smem (split hi/lo, swizzled)
#pragma unroll
        for (int i = 0; i < 4; i++) {
            int v = tid + i * 256;
            {   // A: 128 rows x 32 k ; 128B line covers 2 rows; 8 16B-chunks swizzled
                int r = v >> 3, kq = (v & 7) << 2;
                int c = kq >> 3, half = (kq >> 2) & 1;
                unsigned off = (unsigned)((r >> 1) * 128 +
                               ((((r & 1) * 4 + c) ^ ((r >> 1) & 7)) << 4) + half * 8);
                float f[4] = {pa[i].x, pa[i].y, pa[i].z, pa[i].w};
                __nv_bfloat16 h[4], l[4];
#pragma unroll
                for (int j = 0; j < 4; j++) {
                    h[j] = __float2bfloat16(f[j]);
                    l[j] = __float2bfloat16(f[j] - __bfloat162float(h[j]));
                }
                *reinterpret_cast<uint2*>((char*)Ah + off) = *reinterpret_cast<uint2*>(h);
                *reinterpret_cast<uint2*>((char*)Al + off) = *reinterpret_cast<uint2*>(l);
            }
            {   // B: 32 k-rows x 128 n ; 256B rows, 16 chunks, xor k&7
                int kr = v >> 5, nq = (v & 31) << 2;
                int c = nq >> 3, half = (nq >> 2) & 1;
                unsigned off = (unsigned)(kr * 256 + ((c ^ (kr & 7)) << 4) + half * 8);
                float f[4] = {pb[i].x, pb[i].y, pb[i].z, pb[i].w};
                __nv_bfloat16 h[4], l[4];
#pragma unroll
                for (int j = 0; j < 4; j++) {
                    h[j] = __float2bfloat16(f[j]);
                    l[j] = __float2bfloat16(f[j] - __bfloat162float(h[j]));
                }
                *reinterpret_cast<uint2*>((char*)Bh + off) = *reinterpret_cast<uint2*>(h);
                *reinterpret_cast<uint2*>((char*)Bl + off) = *reinterpret_cast<uint2*>(l);
            }
        }
        __syncthreads();

        // prefetch next tile (overlaps with compute below)
        if (kt + 1 < nk) {
#pragma unroll
            for (int i = 0; i < 4; i++) {
                int v = tid + i * 256;
                int r = v >> 3, kq = (v & 7) << 2;
                pa[i] = *reinterpret_cast<const float4*>(
                    A + (size_t)(row0 + r) * K + (kt + 1) * 32 + kq);
                int kr = v >> 5, nq = (v & 31) << 2;
                pb[i] = *reinterpret_cast<const float4*>(
                    B + (size_t)((kt + 1) * 32 + kr) * N + col0 + nq);
            }
        }

        const int tI = lane >> 3;   // ldmatrix sub-tile index
        const int rI = lane & 7;
        const unsigned ah_base = sptr(Ah), al_base = sptr(Al);
        const unsigned bh_base = sptr(Bh), bl_base = sptr(Bl);

#pragma unroll
        for (int ks = 0; ks < 2; ks++) {          // two k16 steps per k32 tile
            unsigned afh[4][4], afl[4][4];
#pragma unroll
            for (int mt = 0; mt < 4; mt++) {
                int r   = wm * 64 + mt * 16 + rI + ((tI & 1) << 3);
                int cch = (ks << 1) + (tI >> 1);
                unsigned off = (unsigned)((r >> 1) * 128 +
                               ((((r & 1) * 4 + cch) ^ ((r >> 1) & 7)) << 4));
                ldsm_x4(afh[mt], ah_base + off);
                ldsm_x4(afl[mt], al_base + off);
            }
            unsigned bfh[2][4], bfl[2][4];
#pragma unroll
            for (int nb = 0; nb < 2; nb++) {      // each covers 16 n
                int k   = (ks << 4) + rI + ((tI & 1) << 3);
                int cch = ((wn * 32 + nb * 16) >> 3) + (tI >> 1);
                unsigned off = (unsigned)(k * 256 + ((cch ^ (k & 7)) << 4));
                ldsm_x4_t(bfh[nb], bh_base + off);
                ldsm_x4_t(bfl[nb], bl_base + off);
            }
#pragma unroll
            for (int mt = 0; mt < 4; mt++)
#pragma unroll
                for (int nt = 0; nt < 4; nt++) {
                    const unsigned* bh = &bfh[nt >> 1][(nt & 1) * 2];
                    const unsigned* bl = &bfl[nt >> 1][(nt & 1) * 2];
                    mma16816(acc[mt][nt], afh[mt], bh);
                    mma16816(acc[mt][nt], afh[mt], bl);
                    mma16816(acc[mt][nt], afl[mt], bh);
                }
        }
        __syncthreads();
    }

    // epilogue
#pragma unroll
    for (int mt = 0; mt < 4; mt++) {
#pragma unroll
        for (int half = 0; half < 2; half++) {
            int r = row0 + wm * 64 + mt * 16 + (lane >> 2) + half * 8;
            float d = (MODE == 1) ? deg[r] : 1.f;
#pragma unroll
            for (int nt = 0; nt < 4; nt++) {
                int c = col0 + wn * 32 + nt * 8 + (lane & 3) * 2;
                float v0 = acc[mt][nt][half * 2 + 0];
                float v1 = acc[mt][nt][half * 2 + 1];
                if (MODE == 1) {
                    const float2 z = *reinterpret_cast<const float2*>(Zadd + (size_t)r * N + c);
                    v0 = (v0 + z.x) / d; v1 = (v1 + z.y) / d;
                    v0 = (v0 > 0.f) ? v0 : expm1f(v0);
                    v1 = (v1 > 0.f) ? v1 : expm1f(v1);
                }
                *reinterpret_cast<float2*>(C + (size_t)r * N + c) = make_float2(v0, v1);
            }
        }
    }
}

// ---------------- similarity graph: s2 = x @ (W @ a2), top-16 hubs ----------------
__global__ void w2v_kernel(const float* __restrict__ W, const float* __restrict__ a2,
                           float* __restrict__ w2v) {
    int r = blockIdx.x * blockDim.x + threadIdx.x;
    if (r < IN_F) {
        float s = 0.f;
        for (int j = 0; j < HF; j++) s += W[(size_t)r * HF + j] * a2[j];
        w2v[r] = s;
    }
}

__global__ void s2_kernel(const float* __restrict__ x, const float* __restrict__ w2v,
                          float* __restrict__ s2) {
    int w    = (blockIdx.x * blockDim.x + threadIdx.x) >> 5;
    int lane = threadIdx.x & 31;
    if (w >= NN) return;
    const float* xr = x + (size_t)w * IN_F;
    float s = 0.f;
    for (int j = lane; j < IN_F; j += 32) s += xr[j] * w2v[j];
#pragma unroll
    for (int o = 16; o; o >>= 1) s += __shfl_xor_sync(0xffffffffu, s, o);
    if (lane == 0) s2[w] = s;
}

__global__ void top16_kernel(const float* __restrict__ s2, int* __restrict__ hub,
                             int* __restrict__ hubflag) {
    __shared__ float buf[NN];
    __shared__ float sval[256];
    __shared__ int   sidx[256];
    int t = threadIdx.x;
    for (int i = t; i < NN; i += 256) { buf[i] = s2[i]; hubflag[i] = 0; }
    __syncthreads();
    for (int pick = 0; pick < 16; pick++) {
        float best = -INFINITY; int bi = 0;
        for (int i = t; i < NN; i += 256)
            if (buf[i] > best) { best = buf[i]; bi = i; }
        sval[t] = best; sidx[t] = bi;
        __syncthreads();
        for (int s = 128; s > 0; s >>= 1) {
            if (t < s && sval[t + s] > sval[t]) { sval[t] = sval[t + s]; sidx[t] = sidx[t + s]; }
            __syncthreads();
        }
        if (t == 0) { hub[pick] = sidx[0]; hubflag[sidx[0]] = 1; buf[sidx[0]] = -INFINITY; }
        __syncthreads();
    }
}

// ---------------- structural sim-graph aggregation ----------------
__global__ void colsum_kernel(const float* __restrict__ Z, float* __restrict__ total) {
    int c = threadIdx.x;
    size_t r0 = (size_t)blockIdx.x * 64;
    float s = 0.f;
    for (int r = 0; r < 64; r++) s += Z[(r0 + r) * HF + c];
    atomicAdd(&total[c], s);
}

__global__ void s16_kernel(const float* __restrict__ Z, const int* __restrict__ hub,
                           float* __restrict__ S16) {
    int c = threadIdx.x;
    float s = 0.f;
    for (int h = 0; h < 16; h++) s += Z[(size_t)hub[h] * HF + c];
    S16[c] = s;
}

// out[i][c] = elu(  hub ? Total[c]/8192 : (S16[c] + Z[i][c]) / 17 )
__global__ void simagg_kernel(const float* __restrict__ Z, const float* __restrict__ total,
                              const float* __restrict__ S16, const int* __restrict__ hubflag,
                              float* __restrict__ out) {
    int i = blockIdx.x, c = threadIdx.x;
    float v;
    if (hubflag[i]) v = total[c] * (1.0f / 8192.0f);
    else            v = (S16[c] + Z[(size_t)i * HF + c]) / 17.0f;
    out[(size_t)i * HF + c] = (v > 0.f) ? v : expm1f(v);
}

// ---------------- bilinear edge scorer + BCE ----------------
__global__ void edge_kernel(const int* __restrict__ src, const int* __restrict__ dst,
                            const float* __restrict__ labels, const float* __restrict__ P,
                            const float* __restrict__ H, const float* __restrict__ Hb,
                            const float* __restrict__ bias,
                            float* __restrict__ logits, float* __restrict__ pred,
                            float* __restrict__ acc) {
    __shared__ float warpsum[8];
    int lane = threadIdx.x & 31;
    int wid  = threadIdx.x >> 5;
    int e = blockIdx.x * 8 + wid;
    const float* p  = P  + (size_t)src[e] * (2 * HF);
    const float* h  = H  + (size_t)dst[e] * HF;
    const float* hb = Hb + (size_t)dst[e] * HF;
    float s = 0.f;
#pragma unroll 4
    for (int j = lane; j < HF; j += 32) s += p[j] * h[j] + p[HF + j] * hb[j];
#pragma unroll
    for (int o = 16; o; o >>= 1) s += __shfl_xor_sync(0xffffffffu, s, o);
    if (lane == 0) {
        float lg = s + bias[0];
        if (logits) logits[e] = lg;
        if (pred) pred[e] = (lg >= 0.f) ? 1.f : 0.f;
        float l = labels[e];
        warpsum[wid] = fmaxf(lg, 0.f) - lg * l + log1pf(expf(-fabsf(lg)));
    }
    __syncthreads();
    if (threadIdx.x == 0) {
        float t = 0.f;
        for (int i = 0; i < 8; i++) t += warpsum[i];
        atomicAdd(acc, t);
    }
}

__global__ void finalize_kernel(const float* __restrict__ acc, float* __restrict__ out) {
    if (out) out[0] = acc[0] * (1.0f / (float)NEDGE);
}

// ---------------- host ----------------
extern "C" void kernel_launch(void* const* d_in, const int* in_sizes, int n_in,
                              void* d_out, int out_size) {
    const int*   src    = (const int*)  d_in[0];
    const int*   dst    = (const int*)  d_in[1];
    const float* labels = (const float*)d_in[2];
    const float* adj    = (const float*)d_in[3];
    const float* x      = (const float*)d_in[4];
    const float* W1_0   = (const float*)d_in[5];
    const float* W1_1   = (const float*)d_in[6];
    const float* W2_0   = (const float*)d_in[7];
    const float* W2_1   = (const float*)d_in[8];
    const float* W      = (const float*)d_in[9];
    const float* a2     = (const float*)d_in[11];
    const float* bil_w  = (const float*)d_in[12];
    const float* bil_b  = (const float*)d_in[13];

    float *pZ, *pH1, *pH, *pHb, *pP, *pdeg, *ps2, *pw2v, *ptotA, *ptotB, *pS16, *pacc;
    int *phub, *phubflag;
    cudaGetSymbolAddress((void**)&pZ, g_Z);       cudaGetSymbolAddress((void**)&pH1, g_H1);
    cudaGetSymbolAddress((void**)&pH, g_H);       cudaGetSymbolAddress((void**)&pHb, g_Hb);
    cudaGetSymbolAddress((void**)&pP, g_P);       cudaGetSymbolAddress((void**)&pdeg, g_deg);
    cudaGetSymbolAddress((void**)&ps2, g_s2);     cudaGetSymbolAddress((void**)&pw2v, g_w2v);
    cudaGetSymbolAddress((void**)&ptotA, g_totA); cudaGetSymbolAddress((void**)&ptotB, g_totB);
    cudaGetSymbolAddress((void**)&pS16, g_S16);   cudaGetSymbolAddress((void**)&pacc, g_acc);
    cudaGetSymbolAddress((void**)&phub, g_hub);   cudaGetSymbolAddress((void**)&phubflag, g_hubflag);

    float* out = (float*)d_out;
    float *loss_ptr = nullptr, *logits_ptr = nullptr, *pred_ptr = nullptr;
    if (out_size >= 1 + 2 * NEDGE) {          // (loss, logits, predict) flattened
        loss_ptr = out; logits_ptr = out + 1; pred_ptr = out + 1 + NEDGE;
    } else if (out_size >= 2 * NEDGE) {       // (logits, predict)
        logits_ptr = out; pred_ptr = out + NEDGE;
    } else {                                   // logits only (or loss only)
        logits_ptr = out;
    }

    init_kernel<<<32, 256>>>(pdeg, ptotA, ptotB, pacc);
    deg_kernel<<<dim3(32, 16), 256>>>(adj, pdeg);

    // GCN 1 on adj:  h
    mma_gemm<0><<<dim3(2, 64), 256>>>(x,   W1_0, pZ,  NN, HF, IN_F, nullptr, nullptr);
    mma_gemm<1><<<dim3(2, 64), 256>>>(adj, pZ,   pH1, NN, HF, NN,   pZ, pdeg);
    mma_gemm<0><<<dim3(2, 64), 256>>>(pH1, W1_1, pZ,  NN, HF, HF,   nullptr, nullptr);
    mma_gemm<1><<<dim3(2, 64), 256>>>(adj, pZ,   pH,  NN, HF, NN,   pZ, pdeg);

    // similarity graph structure (only s2 ordering matters)
    w2v_kernel<<<2, 256>>>(W, a2, pw2v);
    s2_kernel<<<NN / 8, 256>>>(x, pw2v, ps2);
    top16_kernel<<<1, 256>>>(ps2, phub, phubflag);

    // GCN 2 on sim graph (structural aggregation):  h_
    mma_gemm<0><<<dim3(2, 64), 256>>>(x, W2_0, pZ, NN, HF, IN_F, nullptr, nullptr);
    colsum_kernel<<<128, 256>>>(pZ, ptotA);
    s16_kernel<<<1, 256>>>(pZ, phub, pS16);
    simagg_kernel<<<NN, 256>>>(pZ, ptotA, pS16, phubflag, pH1);
    mma_gemm<0><<<dim3(2, 64), 256>>>(pH1, W2_1, pZ, NN, HF, HF, nullptr, nullptr);
    colsum_kernel<<<128, 256>>>(pZ, ptotB);
    s16_kernel<<<1, 256>>>(pZ, phub, pS16);
    simagg_kernel<<<NN, 256>>>(pZ, ptotB, pS16, phubflag, pHb);

    // bilinear head: P = x @ bil_w, then per-edge dot + BCE
    mma_gemm<0><<<dim3(4, 64), 256>>>(x, bil_w, pP, NN, 2 * HF, IN_F, nullptr, nullptr);
    edge_kernel<<<NEDGE / 8, 256>>>(src, dst, labels, pP, pH, pHb, bil_b,
                                    logits_ptr, pred_ptr, pacc);
    finalize_kernel<<<1, 1>>>(pacc, loss_ptr);
}

// round 17
// speedup vs baseline: 1.0141x; 1.0141x over previous
#include <cuda_runtime.h>
#include <cuda_bf16.h>
#include <cstdint>
#include <stdint.h>
#include <math.h>

#define NN    8192
#define IN_F  512
#define HF    256
#define NEDGE 65536

// dynamic smem: 2 stages x 32KB  (Ah 8K | Al 8K | Bh 8K | Bl 8K per stage)
#define STAGE_BYTES 32768
#define SMEM_TOTAL  (2 * STAGE_BYTES)

// ---------------- scratch (device globals; no allocation allowed) ----------------
__device__ float g_Z [NN * HF];
__device__ float g_H1[NN * HF];
__device__ float g_H [NN * HF];   // h  (GCN on adj)
__device__ float g_Hb[NN * HF];   // h_ (GCN on sim graph)
__device__ float g_P [NN * 2 * HF];
__device__ float g_deg[NN];
__device__ float g_s2 [NN];
__device__ float g_w2v[IN_F];
__device__ float g_totA[HF];
__device__ float g_totB[HF];
__device__ float g_S16[HF];
__device__ int   g_hub[16];
__device__ int   g_hubflag[NN];
__device__ float g_acc;

// ---------------- small helpers ----------------
__device__ __forceinline__ unsigned sptr(const void* p) {
    return (unsigned)__cvta_generic_to_shared(p);
}
__device__ __forceinline__ void ldsm_x4(unsigned r[4], unsigned addr) {
    asm volatile("ldmatrix.sync.aligned.m8n8.x4.shared.b16 {%0,%1,%2,%3}, [%4];"
        : "=r"(r[0]), "=r"(r[1]), "=r"(r[2]), "=r"(r[3]) : "r"(addr));
}
__device__ __forceinline__ void ldsm_x4_t(unsigned r[4], unsigned addr) {
    asm volatile("ldmatrix.sync.aligned.m8n8.x4.trans.shared.b16 {%0,%1,%2,%3}, [%4];"
        : "=r"(r[0]), "=r"(r[1]), "=r"(r[2]), "=r"(r[3]) : "r"(addr));
}
__device__ __forceinline__ void mma16816(float c[4], const unsigned a[4], const unsigned b[2]) {
    asm volatile("mma.sync.aligned.m16n8k16.row.col.f32.bf16.bf16.f32 "
        "{%0,%1,%2,%3}, {%4,%5,%6,%7}, {%8,%9}, {%0,%1,%2,%3};"
        : "+f"(c[0]), "+f"(c[1]), "+f"(c[2]), "+f"(c[3])
        : "r"(a[0]), "r"(a[1]), "r"(a[2]), "r"(a[3]), "r"(b[0]), "r"(b[1]));
}

// convert fp32 tile (in registers) to split-bf16 and store into one smem stage
__device__ __forceinline__ void cvt_store(char* base, int tid,
                                          const float4* pa, const float4* pb) {
    char* sAh = base;
    char* sAl = base + 8192;
    char* sBh = base + 16384;
    char* sBl = base + 24576;
#pragma unroll
    for (int i = 0; i < 4; i++) {
        int v = tid + i * 256;
        {   // A: 128 rows x 32 k ; 128B line covers 2 rows; 8 16B-chunks swizzled
            int r = v >> 3, kq = (v & 7) << 2;
            int c = kq >> 3, half = (kq >> 2) & 1;
            unsigned off = (unsigned)((r >> 1) * 128 +
                           ((((r & 1) * 4 + c) ^ ((r >> 1) & 7)) << 4) + half * 8);
            float f[4] = {pa[i].x, pa[i].y, pa[i].z, pa[i].w};
            __nv_bfloat16 h[4], l[4];
#pragma unroll
            for (int j = 0; j < 4; j++) {
                h[j] = __float2bfloat16(f[j]);
                l[j] = __float2bfloat16(f[j] - __bfloat162float(h[j]));
            }
            *reinterpret_cast<uint2*>(sAh + off) = *reinterpret_cast<uint2*>(h);
            *reinterpret_cast<uint2*>(sAl + off) = *reinterpret_cast<uint2*>(l);
        }
        {   // B: 32 k-rows x 128 n ; 256B rows, 16 chunks, xor k&7
            int kr = v >> 5, nq = (v & 31) << 2;
            int c = nq >> 3, half = (nq >> 2) & 1;
            unsigned off = (unsigned)(kr * 256 + ((c ^ (kr & 7)) << 4) + half * 8);
            float f[4] = {pb[i].x, pb[i].y, pb[i].z, pb[i].w};
            __nv_bfloat16 h[4], l[4];
#pragma unroll
            for (int j = 0; j < 4; j++) {
                h[j] = __float2bfloat16(f[j]);
                l[j] = __float2bfloat16(f[j] - __bfloat162float(h[j]));
            }
            *reinterpret_cast<uint2*>(sBh + off) = *reinterpret_cast<uint2*>(h);
            *reinterpret_cast<uint2*>(sBl + off) = *reinterpret_cast<uint2*>(l);
        }
    }
}

// ---------------- init ----------------
__global__ void init_kernel(float* deg, float* totA, float* totB, float* acc) {
    int i = blockIdx.x * blockDim.x + threadIdx.x;
    if (i < NN) deg[i] = 1.0f;           // +I contribution to column sums
    if (i < HF) { totA[i] = 0.f; totB[i] = 0.f; }
    if (i == 0) acc[0] = 0.f;
}

// deg[c] = 1 + sum_r adj[r][c]  (column sums of adj+I)
__global__ void deg_kernel(const float* __restrict__ adj, float* __restrict__ deg) {
    int c = blockIdx.x * 256 + threadIdx.x;
    size_t r0 = (size_t)blockIdx.y * 512;
    float s = 0.f;
    for (int r = 0; r < 512; r++) s += adj[(r0 + r) * NN + c];
    atomicAdd(&deg[c], s);
}

// ---------------- split-bf16 tensor-core GEMM, 128x128x32 CTA tile ----------------
// Double-buffered smem pipeline: convert+store of tile kt+1 overlaps MMA of kt.
// C = A@B in "effective fp32": Ahi*Bhi + Ahi*Blo + Alo*Bhi  (fp32 accum)
// MODE 0: C = A@B
// MODE 1: C = elu((A@B + Zadd)/deg[row])      [ (adj+I)Z normalized ]
template <int MODE>
__global__ void __launch_bounds__(256, 1)
mma_gemm(const float* __restrict__ A, const float* __restrict__ B,
         float* __restrict__ C, int M, int N, int K,
         const float* __restrict__ Zadd, const float* __restrict__ deg)
{
    extern __shared__ __align__(16) char smem_raw[];

    const int tid  = threadIdx.x;
    const int lane = tid & 31;
    const int w    = tid >> 5;
    const int wm   = w & 1;        // 2 warps along M (64 rows each)
    const int wn   = w >> 1;       // 4 warps along N (32 cols each)
    const int row0 = blockIdx.y * 128;
    const int col0 = blockIdx.x * 128;

    float acc[4][4][4];
#pragma unroll
    for (int mt = 0; mt < 4; mt++)
#pragma unroll
        for (int nt = 0; nt < 4; nt++)
#pragma unroll
            for (int q = 0; q < 4; q++) acc[mt][nt][q] = 0.f;

    float4 pa[4], pb[4];
    const int nk = K >> 5;

    // prologue: load + convert + store tile 0 into stage 0
#pragma unroll
    for (int i = 0; i < 4; i++) {
        int v = tid + i * 256;
        int r = v >> 3, kq = (v & 7) << 2;
        pa[i] = *reinterpret_cast<const float4*>(A + (size_t)(row0 + r) * K + kq);
        int kr = v >> 5, nq = (v & 31) << 2;
        pb[i] = *reinterpret_cast<const float4*>(B + (size_t)kr * N + col0 + nq);
    }
    cvt_store(smem_raw, tid, pa, pb);
    __syncthreads();

    const int tI = lane >> 3;   // ldmatrix sub-tile index
    const int rI = lane & 7;

    for (int kt = 0; kt < nk; kt++) {
        const int cur = kt & 1;
        char* base_c = smem_raw + cur * STAGE_BYTES;

        // issue global loads for tile kt+1 early (latency hidden under MMA)
        if (kt + 1 < nk) {
#pragma unroll
            for (int i = 0; i < 4; i++) {
                int v = tid + i * 256;
                int r = v >> 3, kq = (v & 7) << 2;
                pa[i] = *reinterpret_cast<const float4*>(
                    A + (size_t)(row0 + r) * K + (kt + 1) * 32 + kq);
                int kr = v >> 5, nq = (v & 31) << 2;
                pb[i] = *reinterpret_cast<const float4*>(
                    B + (size_t)((kt + 1) * 32 + kr) * N + col0 + nq);
            }
        }

        const unsigned ah_base = sptr(base_c);
        const unsigned al_base = ah_base + 8192;
        const unsigned bh_base = ah_base + 16384;
        const unsigned bl_base = ah_base + 24576;

#pragma unroll
        for (int ks = 0; ks < 2; ks++) {          // two k16 steps per k32 tile
            unsigned afh[4][4], afl[4][4];
#pragma unroll
            for (int mt = 0; mt < 4; mt++) {
                int r   = wm * 64 + mt * 16 + rI + ((tI & 1) << 3);
                int cch = (ks << 1) + (tI >> 1);
                unsigned off = (unsigned)((r >> 1) * 128 +
                               ((((r & 1) * 4 + cch) ^ ((r >> 1) & 7)) << 4));
                ldsm_x4(afh[mt], ah_base + off);
                ldsm_x4(afl[mt], al_base + off);
            }
            unsigned bfh[2][4], bfl[2][4];
#pragma unroll
            for (int nb = 0; nb < 2; nb++) {      // each covers 16 n
                int k   = (ks << 4) + rI + ((tI & 1) << 3);
                int cch = ((wn * 32 + nb * 16) >> 3) + (tI >> 1);
                unsigned off = (unsigned)(k * 256 + ((cch ^ (k & 7)) << 4));
                ldsm_x4_t(bfh[nb], bh_base + off);
                ldsm_x4_t(bfl[nb], bl_base + off);
            }
#pragma unroll
            for (int mt = 0; mt < 4; mt++)
#pragma unroll
                for (int nt = 0; nt < 4; nt++) {
                    const unsigned* bh = &bfh[nt >> 1][(nt & 1) * 2];
                    const unsigned* bl = &bfl[nt >> 1][(nt & 1) * 2];
                    mma16816(acc[mt][nt], afh[mt], bh);
                    mma16816(acc[mt][nt], afh[mt], bl);
                    mma16816(acc[mt][nt], afl[mt], bh);
                }
        }

        // convert+store tile kt+1 into the other stage (overlaps MMA drain)
        if (kt + 1 < nk) {
            cvt_store(smem_raw + (cur ^ 1) * STAGE_BYTES, tid, pa, pb);
        }
        __syncthreads();
    }

    // epilogue
#pragma unroll
    for (int mt = 0; mt < 4; mt++) {
#pragma unroll
        for (int half = 0; half < 2; half++) {
            int r = row0 + wm * 64 + mt * 16 + (lane >> 2) + half * 8;
            float d = (MODE == 1) ? deg[r] : 1.f;
#pragma unroll
            for (int nt = 0; nt < 4; nt++) {
                int c = col0 + wn * 32 + nt * 8 + (lane & 3) * 2;
                float v0 = acc[mt][nt][half * 2 + 0];
                float v1 = acc[mt][nt][half * 2 + 1];
                if (MODE == 1) {
                    const float2 z = *reinterpret_cast<const float2*>(Zadd + (size_t)r * N + c);
                    v0 = (v0 + z.x) / d; v1 = (v1 + z.y) / d;
                    v0 = (v0 > 0.f) ? v0 : expm1f(v0);
                    v1 = (v1 > 0.f) ? v1 : expm1f(v1);
                }
                *reinterpret_cast<float2*>(C + (size_t)r * N + c) = make_float2(v0, v1);
            }
        }
    }
}

// ---------------- similarity graph: s2 = x @ (W @ a2), top-16 hubs ----------------
__global__ void w2v_kernel(const float* __restrict__ W, const float* __restrict__ a2,
                           float* __restrict__ w2v) {
    int r = blockIdx.x * blockDim.x + threadIdx.x;
    if (r < IN_F) {
        float s = 0.f;
        for (int j = 0; j < HF; j++) s += W[(size_t)r * HF + j] * a2[j];
        w2v[r] = s;
    }
}

__global__ void s2_kernel(const float* __restrict__ x, const float* __restrict__ w2v,
                          float* __restrict__ s2) {
    int w    = (blockIdx.x * blockDim.x + threadIdx.x) >> 5;
    int lane = threadIdx.x & 31;
    if (w >= NN) return;
    const float* xr = x + (size_t)w * IN_F;
    float s = 0.f;
    for (int j = lane; j < IN_F; j += 32) s += xr[j] * w2v[j];
#pragma unroll
    for (int o = 16; o; o >>= 1) s += __shfl_xor_sync(0xffffffffu, s, o);
    if (lane == 0) s2[w] = s;
}

__global__ void top16_kernel(const float* __restrict__ s2, int* __restrict__ hub,
                             int* __restrict__ hubflag) {
    __shared__ float buf[NN];
    __shared__ float sval[256];
    __shared__ int   sidx[256];
    int t = threadIdx.x;
    for (int i = t; i < NN; i += 256) { buf[i] = s2[i]; hubflag[i] = 0; }
    __syncthreads();
    for (int pick = 0; pick < 16; pick++) {
        float best = -INFINITY; int bi = 0;
        for (int i = t; i < NN; i += 256)
            if (buf[i] > best) { best = buf[i]; bi = i; }
        sval[t] = best; sidx[t] = bi;
        __syncthreads();
        for (int s = 128; s > 0; s >>= 1) {
            if (t < s && sval[t + s] > sval[t]) { sval[t] = sval[t + s]; sidx[t] = sidx[t + s]; }
            __syncthreads();
        }
        if (t == 0) { hub[pick] = sidx[0]; hubflag[sidx[0]] = 1; buf[sidx[0]] = -INFINITY; }
        __syncthreads();
    }
}

// ---------------- structural sim-graph aggregation ----------------
__global__ void colsum_kernel(const float* __restrict__ Z, float* __restrict__ total) {
    int c = threadIdx.x;
    size_t r0 = (size_t)blockIdx.x * 64;
    float s = 0.f;
    for (int r = 0; r < 64; r++) s += Z[(r0 + r) * HF + c];
    atomicAdd(&total[c], s);
}

__global__ void s16_kernel(const float* __restrict__ Z, const int* __restrict__ hub,
                           float* __restrict__ S16) {
    int c = threadIdx.x;
    float s = 0.f;
    for (int h = 0; h < 16; h++) s += Z[(size_t)hub[h] * HF + c];
    S16[c] = s;
}

// out[i][c] = elu(  hub ? Total[c]/8192 : (S16[c] + Z[i][c]) / 17 )
__global__ void simagg_kernel(const float* __restrict__ Z, const float* __restrict__ total,
                              const float* __restrict__ S16, const int* __restrict__ hubflag,
                              float* __restrict__ out) {
    int i = blockIdx.x, c = threadIdx.x;
    float v;
    if (hubflag[i]) v = total[c] * (1.0f / 8192.0f);
    else            v = (S16[c] + Z[(size_t)i * HF + c]) / 17.0f;
    out[(size_t)i * HF + c] = (v > 0.f) ? v : expm1f(v);
}

// ---------------- bilinear edge scorer + BCE ----------------
__global__ void edge_kernel(const int* __restrict__ src, const int* __restrict__ dst,
                            const float* __restrict__ labels, const float* __restrict__ P,
                            const float* __restrict__ H, const float* __restrict__ Hb,
                            const float* __restrict__ bias,
                            float* __restrict__ logits, float* __restrict__ pred,
                            float* __restrict__ acc) {
    __shared__ float warpsum[8];
    int lane = threadIdx.x & 31;
    int wid  = threadIdx.x >> 5;
    int e = blockIdx.x * 8 + wid;
    const float* p  = P  + (size_t)src[e] * (2 * HF);
    const float* h  = H  + (size_t)dst[e] * HF;
    const float* hb = Hb + (size_t)dst[e] * HF;
    float s = 0.f;
#pragma unroll 4
    for (int j = lane; j < HF; j += 32) s += p[j] * h[j] + p[HF + j] * hb[j];
#pragma unroll
    for (int o = 16; o; o >>= 1) s += __shfl_xor_sync(0xffffffffu, s, o);
    if (lane == 0) {
        float lg = s + bias[0];
        if (logits) logits[e] = lg;
        if (pred) pred[e] = (lg >= 0.f) ? 1.f : 0.f;
        float l = labels[e];
        warpsum[wid] = fmaxf(lg, 0.f) - lg * l + log1pf(expf(-fabsf(lg)));
    }
    __syncthreads();
    if (threadIdx.x == 0) {
        float t = 0.f;
        for (int i = 0; i < 8; i++) t += warpsum[i];
        atomicAdd(acc, t);
    }
}

__global__ void finalize_kernel(const float* __restrict__ acc, float* __restrict__ out) {
    if (out) out[0] = acc[0] * (1.0f / (float)NEDGE);
}

// ---------------- host ----------------
extern "C" void kernel_launch(void* const* d_in, const int* in_sizes, int n_in,
                              void* d_out, int out_size) {
    const int*   src    = (const int*)  d_in[0];
    const int*   dst    = (const int*)  d_in[1];
    const float* labels = (const float*)d_in[2];
    const float* adj    = (const float*)d_in[3];
    const float* x      = (const float*)d_in[4];
    const float* W1_0   = (const float*)d_in[5];
    const float* W1_1   = (const float*)d_in[6];
    const float* W2_0   = (const float*)d_in[7];
    const float* W2_1   = (const float*)d_in[8];
    const float* W      = (const float*)d_in[9];
    const float* a2     = (const float*)d_in[11];
    const float* bil_w  = (const float*)d_in[12];
    const float* bil_b  = (const float*)d_in[13];

    float *pZ, *pH1, *pH, *pHb, *pP, *pdeg, *ps2, *pw2v, *ptotA, *ptotB, *pS16, *pacc;
    int *phub, *phubflag;
    cudaGetSymbolAddress((void**)&pZ, g_Z);       cudaGetSymbolAddress((void**)&pH1, g_H1);
    cudaGetSymbolAddress((void**)&pH, g_H);       cudaGetSymbolAddress((void**)&pHb, g_Hb);
    cudaGetSymbolAddress((void**)&pP, g_P);       cudaGetSymbolAddress((void**)&pdeg, g_deg);
    cudaGetSymbolAddress((void**)&ps2, g_s2);     cudaGetSymbolAddress((void**)&pw2v, g_w2v);
    cudaGetSymbolAddress((void**)&ptotA, g_totA); cudaGetSymbolAddress((void**)&ptotB, g_totB);
    cudaGetSymbolAddress((void**)&pS16, g_S16);   cudaGetSymbolAddress((void**)&pacc, g_acc);
    cudaGetSymbolAddress((void**)&phub, g_hub);   cudaGetSymbolAddress((void**)&phubflag, g_hubflag);

    // allow 64KB dynamic smem for the GEMM (idempotent; no allocation)
    cudaFuncSetAttribute(mma_gemm<0>, cudaFuncAttributeMaxDynamicSharedMemorySize, SMEM_TOTAL);
    cudaFuncSetAttribute(mma_gemm<1>, cudaFuncAttributeMaxDynamicSharedMemorySize, SMEM_TOTAL);

    float* out = (float*)d_out;
    float *loss_ptr = nullptr, *logits_ptr = nullptr, *pred_ptr = nullptr;
    if (out_size >= 1 + 2 * NEDGE) {          // (loss, logits, predict) flattened
        loss_ptr = out; logits_ptr = out + 1; pred_ptr = out + 1 + NEDGE;
    } else if (out_size >= 2 * NEDGE) {       // (logits, predict)
        logits_ptr = out; pred_ptr = out + NEDGE;
    } else {                                   // logits only (or loss only)
        logits_ptr = out;
    }

    init_kernel<<<32, 256>>>(pdeg, ptotA, ptotB, pacc);
    deg_kernel<<<dim3(32, 16), 256>>>(adj, pdeg);

    // GCN 1 on adj:  h
    mma_gemm<0><<<dim3(2, 64), 256, SMEM_TOTAL>>>(x,   W1_0, pZ,  NN, HF, IN_F, nullptr, nullptr);
    mma_gemm<1><<<dim3(2, 64), 256, SMEM_TOTAL>>>(adj, pZ,   pH1, NN, HF, NN,   pZ, pdeg);
    mma_gemm<0><<<dim3(2, 64), 256, SMEM_TOTAL>>>(pH1, W1_1, pZ,  NN, HF, HF,   nullptr, nullptr);
    mma_gemm<1><<<dim3(2, 64), 256, SMEM_TOTAL>>>(adj, pZ,   pH,  NN, HF, NN,   pZ, pdeg);

    // similarity graph structure (only s2 ordering matters)
    w2v_kernel<<<2, 256>>>(W, a2, pw2v);
    s2_kernel<<<NN / 8, 256>>>(x, pw2v, ps2);
    top16_kernel<<<1, 256>>>(ps2, phub, phubflag);

    // GCN 2 on sim graph (structural aggregation):  h_
    mma_gemm<0><<<dim3(2, 64), 256, SMEM_TOTAL>>>(x, W2_0, pZ, NN, HF, IN_F, nullptr, nullptr);
    colsum_kernel<<<128, 256>>>(pZ, ptotA);
    s16_kernel<<<1, 256>>>(pZ, phub, pS16);
    simagg_kernel<<<NN, 256>>>(pZ, ptotA, pS16, phubflag, pH1);
    mma_gemm<0><<<dim3(2, 64), 256, SMEM_TOTAL>>>(pH1, W2_1, pZ, NN, HF, HF, nullptr, nullptr);
    colsum_kernel<<<128, 256>>>(pZ, ptotB);
    s16_kernel<<<1, 256>>>(pZ, phub, pS16);
    simagg_kernel<<<NN, 256>>>(pZ, ptotB, pS16, phubflag, pHb);

    // bilinear head: P = x @ bil_w, then per-edge dot + BCE
    mma_gemm<0><<<dim3(4, 64), 256, SMEM_TOTAL>>>(x, bil_w, pP, NN, 2 * HF, IN_F, nullptr, nullptr);
    edge_kernel<<<NEDGE / 8, 256>>>(src, dst, labels, pP, pH, pHb, bil_b,
                                    logits_ptr, pred_ptr, pacc);
    finalize_kernel<<<1, 1>>>(pacc, loss_ptr);
}